// round 8
// baseline (speedup 1.0000x reference)
#include <cuda_runtime.h>
#include <cuda_bf16.h>
#include <math.h>
#include <stdint.h>

#define N_NODES 8192
#define DIM     512
#define TOPK_K  20
#define NCAND   32
#define NTILES  64                         // N_NODES / 128
#define CAND_PER_TILE 16                   // 8 per 64-col half (wn half-tiles)
#define NC_TOT  (NTILES * CAND_PER_TILE)   // 1024 candidates per row
#define K3      1536                       // 3 * DIM (split-bf16 concat)
#define ALPHA   0.044194173824159216f      // 1/sqrt(512) (approx path only)
#define SQRTD   22.62741699796952f         // fp32(sqrt(512)) (exact path: divide)

#define NEG_INF __int_as_float(0xff800000)

// ---------------- device scratch (static globals, no runtime alloc) --------
__device__ __nv_bfloat16 g_A[(size_t)N_NODES * K3];     // [Q_hi | Q_hi | Q_lo]
__device__ __nv_bfloat16 g_B[(size_t)N_NODES * K3];     // [K_hi | K_lo | K_hi]
__device__ float         g_Q[(size_t)N_NODES * DIM];    // exact fp32 Q
__device__ float         g_K[(size_t)N_NODES * DIM];    // exact fp32 K
// per-row, per-64-col-half top-8 (value, col) candidates
__device__ float2        g_cand[(size_t)N_NODES * NC_TOT];

// ============================ PTX helpers ==================================
__device__ __forceinline__ uint32_t smem_u32(const void* p) {
    uint32_t a;
    asm("{ .reg .u64 t; cvta.to.shared.u64 t, %1; cvt.u32.u64 %0, t; }"
        : "=r"(a) : "l"(p));
    return a;
}
__device__ __forceinline__ void cp_async16(uint32_t dst, const void* src) {
    asm volatile("cp.async.cg.shared.global [%0], [%1], 16;" :: "r"(dst), "l"(src));
}
#define CP_COMMIT()   asm volatile("cp.async.commit_group;" ::: "memory")
#define CP_WAIT(N)    asm volatile("cp.async.wait_group %0;" :: "n"(N) : "memory")

#define LDSM_X4(r, addr)                                                       \
    asm volatile("ldmatrix.sync.aligned.m8n8.x4.shared.b16 {%0,%1,%2,%3}, [%4];" \
        : "=r"((r)[0]), "=r"((r)[1]), "=r"((r)[2]), "=r"((r)[3]) : "r"(addr))

__device__ __forceinline__ void mma16816(float* c, const uint32_t* a,
                                         const uint32_t* b) {
    asm volatile(
        "mma.sync.aligned.m16n8k16.row.col.f32.bf16.bf16.f32 "
        "{%0,%1,%2,%3}, {%4,%5,%6,%7}, {%8,%9}, {%0,%1,%2,%3};"
        : "+f"(c[0]), "+f"(c[1]), "+f"(c[2]), "+f"(c[3])
        : "r"(a[0]), "r"(a[1]), "r"(a[2]), "r"(a[3]), "r"(b[0]), "r"(b[1]));
}

// ===========================================================================
// Stage 1: projections.  C = h @ W^T (fp32 SGEMM, ascending-k accumulation —
// numerics must match the reference; DO NOT reorder the FMA chain).
// Epilogue writes fp32 Q/K AND split-bf16 operands per blockIdx.z.
// ===========================================================================
__global__ void __launch_bounds__(256, 2)
proj_kernel(const float* __restrict__ h, const float* __restrict__ W_q,
            const float* __restrict__ W_k)
{
    constexpr int BM = 128, BN = 128, BK = 8, TM = 8, TN = 8;
    constexpr int Kd = DIM;
    __shared__ float As[BK * BM];
    __shared__ float Bs[BK * BN];

    const int tid  = threadIdx.x;
    const int brow = blockIdx.y;
    const int bcol = blockIdx.x;
    const int z    = blockIdx.z;

    const float* A = h;
    const float* B = z == 0 ? W_q : W_k;

    const float* Ab = A + (size_t)brow * BM * Kd;
    const float* Bb = B + (size_t)bcol * BN * Kd;

    const int trow = tid / 16;
    const int tcol = tid % 16;
    const int innerRow = tid / 2;
    const int innerCol = tid % 2;

    float acc[TM][TN] = {};
    float regM[TM], regN[TN];

    for (int kt = 0; kt < Kd; kt += BK) {
        float4 a4 = *(const float4*)(Ab + (size_t)innerRow * Kd + kt + innerCol * 4);
        float4 b4 = *(const float4*)(Bb + (size_t)innerRow * Kd + kt + innerCol * 4);
        As[(innerCol * 4 + 0) * BM + innerRow] = a4.x;
        As[(innerCol * 4 + 1) * BM + innerRow] = a4.y;
        As[(innerCol * 4 + 2) * BM + innerRow] = a4.z;
        As[(innerCol * 4 + 3) * BM + innerRow] = a4.w;
        Bs[(innerCol * 4 + 0) * BN + innerRow] = b4.x;
        Bs[(innerCol * 4 + 1) * BN + innerRow] = b4.y;
        Bs[(innerCol * 4 + 2) * BN + innerRow] = b4.z;
        Bs[(innerCol * 4 + 3) * BN + innerRow] = b4.w;
        __syncthreads();

        #pragma unroll
        for (int k = 0; k < BK; k++) {
            #pragma unroll
            for (int i = 0; i < TM; i++) regM[i] = As[k * BM + trow * TM + i];
            #pragma unroll
            for (int j = 0; j < TN; j++) regN[j] = Bs[k * BN + tcol * TN + j];
            #pragma unroll
            for (int i = 0; i < TM; i++)
                #pragma unroll
                for (int j = 0; j < TN; j++)
                    acc[i][j] += regM[i] * regN[j];
        }
        __syncthreads();
    }

    __nv_bfloat16* dst = z == 0 ? g_A : g_B;
    float* dstf = z == 0 ? g_Q : g_K;
    #pragma unroll
    for (int i = 0; i < TM; i++) {
        const int gm = brow * BM + trow * TM + i;
        #pragma unroll
        for (int j = 0; j < TN; j += 2) {
            const int gn = bcol * BN + tcol * TN + j;
            float x0 = acc[i][j], x1 = acc[i][j + 1];
            *(float2*)(dstf + (size_t)gm * DIM + gn) = make_float2(x0, x1);
            __nv_bfloat16 h0 = __float2bfloat16(x0);
            __nv_bfloat16 h1 = __float2bfloat16(x1);
            __nv_bfloat16 l0 = __float2bfloat16(x0 - __bfloat162float(h0));
            __nv_bfloat16 l1 = __float2bfloat16(x1 - __bfloat162float(h1));
            __nv_bfloat162 hh; hh.x = h0; hh.y = h1;
            __nv_bfloat162 ll; ll.x = l0; ll.y = l1;
            size_t base = (size_t)gm * K3 + gn;
            if (z == 0) {   // A' = [Q_hi | Q_hi | Q_lo]
                *(__nv_bfloat162*)(dst + base)             = hh;
                *(__nv_bfloat162*)(dst + base + DIM)       = hh;
                *(__nv_bfloat162*)(dst + base + 2 * DIM)   = ll;
            } else {        // B' = [K_hi | K_lo | K_hi]
                *(__nv_bfloat162*)(dst + base)             = hh;
                *(__nv_bfloat162*)(dst + base + DIM)       = ll;
                *(__nv_bfloat162*)(dst + base + 2 * DIM)   = hh;
            }
        }
    }
}

// ===========================================================================
// Stage 2: approx logits tile (128x128) = alpha*A'@B'^T + ps*prior, diag=-inf,
// then per-row, per-64-col-half TOP-8 emitted to g_cand — NO full logits
// store. Each wn half-warp writes its own 8 slots (no cross-warp race).
// prior read with __ldcs (evict-first) to keep A'/B' L2-resident.
// ===========================================================================
constexpr int G_STAGES = 3;
constexpr int G_NKT    = K3 / 64;            // 24 k-tiles
constexpr int G_ABYTES = 128 * 128;
constexpr int G_BBYTES = 128 * 128;
constexpr int G_PAD    = 1024;
constexpr int G_SMEM_TOTAL = G_PAD + G_STAGES * (G_ABYTES + G_BBYTES); // 99328

__device__ __forceinline__ void g2_load_tile(
    uint32_t sA, uint32_t sB, int kt,
    const __nv_bfloat16* Abase, const __nv_bfloat16* Bbase, int tid)
{
    #pragma unroll
    for (int i = 0; i < 8; i++) {
        const bool isA = i < 4;
        const int cc  = isA ? (tid + i * 256) : (tid + (i - 4) * 256);
        const int row = cc >> 3;
        const int kc  = cc & 7;
        const char* g = (const char*)((isA ? Abase : Bbase)
                          + (size_t)row * K3 + (size_t)kt * 64) + (kc << 4);
        uint32_t o = (uint32_t)(row << 7) + (uint32_t)(kc << 4);
        o ^= (o >> 3) & 0x70;                // SW128 swizzle
        cp_async16((isA ? sA : sB) + o, g);
    }
}

__global__ void __launch_bounds__(256, 2)
gemm2_kernel(const float* __restrict__ prior, const float* __restrict__ prior_scale)
{
    extern __shared__ char smem_raw[];
    uint32_t sbase = smem_u32(smem_raw);
    sbase = (sbase + (G_PAD - 1)) & ~(uint32_t)(G_PAD - 1);

    const int tid  = threadIdx.x;
    const int lane = tid & 31;
    const int wid  = tid >> 5;
    const int wm   = wid & 3;
    const int wn   = wid >> 2;
    const int bm   = blockIdx.y;
    const int bn   = blockIdx.x;

    const __nv_bfloat16* Abase = g_A + (size_t)bm * 128 * K3;
    const __nv_bfloat16* Bbase = g_B + (size_t)bn * 128 * K3;

    const uint32_t sA0 = sbase;
    const uint32_t sB0 = sbase + G_STAGES * G_ABYTES;

    float acc[2][8][4] = {};

    #pragma unroll
    for (int s = 0; s < G_STAGES - 1; s++) {
        g2_load_tile(sA0 + s * G_ABYTES, sB0 + s * G_BBYTES, s, Abase, Bbase, tid);
        CP_COMMIT();
    }

    for (int it = 0; it < G_NKT; it++) {
        CP_WAIT(G_STAGES - 2);
        __syncthreads();

        const int pf = it + G_STAGES - 1;
        if (pf < G_NKT) {
            const int s = pf % G_STAGES;
            g2_load_tile(sA0 + s * G_ABYTES, sB0 + s * G_BBYTES, pf,
                         Abase, Bbase, tid);
        }
        CP_COMMIT();

        const int s = it % G_STAGES;
        const uint32_t sA = sA0 + s * G_ABYTES;
        const uint32_t sB = sB0 + s * G_BBYTES;

        #pragma unroll
        for (int ks = 0; ks < 4; ks++) {
            uint32_t a[2][4];
            #pragma unroll
            for (int mi = 0; mi < 2; mi++) {
                const int row = wm * 32 + mi * 16 + (lane & 15);
                uint32_t o = (uint32_t)(row << 7) + (uint32_t)(ks << 5)
                           + (uint32_t)((lane >> 4) << 4);
                o ^= (o >> 3) & 0x70;
                LDSM_X4(a[mi], sA + o);
            }
            uint32_t b[4][4];
            #pragma unroll
            for (int np = 0; np < 4; np++) {
                const int row = wn * 64 + np * 16 + (lane & 7) + ((lane >> 4) << 3);
                uint32_t o = (uint32_t)(row << 7) + (uint32_t)(ks << 5)
                           + (uint32_t)(((lane >> 3) & 1) << 4);
                o ^= (o >> 3) & 0x70;
                LDSM_X4(b[np], sB + o);
            }
            #pragma unroll
            for (int mi = 0; mi < 2; mi++)
                #pragma unroll
                for (int nj = 0; nj < 8; nj++)
                    mma16816(acc[mi][nj], a[mi], &b[nj >> 1][(nj & 1) * 2]);
        }
    }

    // ---- epilogue: per row, per-64-col-half top-8 ---------------------------
    // Row r (within this warp's half) is handled by a quad (lanes 4q..4q+3);
    // each lane holds 16 of the half's 64 values. 8 rounds of quad-max-extract
    // -> g_cand[r][bn][wn*8 .. wn*8+7].
    const float ps = prior_scale[0];
    #pragma unroll
    for (int mi = 0; mi < 2; mi++) {
        #pragma unroll
        for (int hh = 0; hh < 2; hh++) {
            const int r     = bm * 128 + wm * 32 + mi * 16 + (lane >> 2) + hh * 8;
            const int cbase = bn * 128 + wn * 64 + ((lane & 3) << 1);
            float v[16];
            #pragma unroll
            for (int nj = 0; nj < 8; nj++) {
                const int c = cbase + nj * 8;
                const float2 p = __ldcs((const float2*)(prior
                                    + (size_t)r * N_NODES + c));
                float x0 = acc[mi][nj][2 * hh]     * ALPHA + ps * p.x;
                float x1 = acc[mi][nj][2 * hh + 1] * ALPHA + ps * p.y;
                if (r == c)     x0 = NEG_INF;
                if (r == c + 1) x1 = NEG_INF;
                v[2 * nj]     = x0;
                v[2 * nj + 1] = x1;
            }
            // local argmax (cached)
            float bv = v[0]; int bi = 0;
            #pragma unroll
            for (int j = 1; j < 16; j++)
                if (v[j] > bv) { bv = v[j]; bi = j; }

            float myv[2]; int myc[2];
            #pragma unroll
            for (int e = 0; e < 8; e++) {
                float m  = bv;
                int   mc = cbase + ((bi >> 1) << 3) + (bi & 1);
                const int mycol = mc;
                // quad reduce (xor 1, xor 2); tie -> lower column
                float ov = __shfl_xor_sync(0xffffffffu, m, 1);
                int   oc = __shfl_xor_sync(0xffffffffu, mc, 1);
                if (ov > m || (ov == m && oc < mc)) { m = ov; mc = oc; }
                ov = __shfl_xor_sync(0xffffffffu, m, 2);
                oc = __shfl_xor_sync(0xffffffffu, mc, 2);
                if (ov > m || (ov == m && oc < mc)) { m = ov; mc = oc; }
                // winner lane invalidates + rescans
                if (m == bv && mc == mycol) {
                    v[bi] = NEG_INF;
                    bv = v[0]; bi = 0;
                    #pragma unroll
                    for (int j = 1; j < 16; j++)
                        if (v[j] > bv) { bv = v[j]; bi = j; }
                }
                if ((e & 3) == (lane & 3)) { myv[e >> 2] = m; myc[e >> 2] = mc; }
            }
            float2* cb = g_cand + ((size_t)r * NTILES + bn) * CAND_PER_TILE
                       + wn * 8;
            cb[lane & 3]       = make_float2(myv[0], __int_as_float(myc[0]));
            cb[(lane & 3) + 4] = make_float2(myv[1], __int_as_float(myc[1]));
        }
    }
}

// ===========================================================================
// Stage 3: 1024 candidates/row -> top-32 -> exact serial-order fp32 rescore
// (order-compatible with reference accumulation) -> top-20 + softmax + write.
// ===========================================================================
__global__ void __launch_bounds__(256)
topk_softmax_kernel(const float2* __restrict__ cand,
                    const float* __restrict__ Q,
                    const float* __restrict__ Km,
                    const float* __restrict__ prior,
                    const float* __restrict__ prior_scale,
                    float* __restrict__ out)
{
    const int row  = blockIdx.x;
    const int t    = threadIdx.x;
    const int wid  = t >> 5;
    const int lane = t & 31;

    // each thread owns 4 of the row's 1024 candidates (columns are unique)
    float v[4]; int col[4];
    #pragma unroll
    for (int j = 0; j < 4; j++) {
        const float2 c = cand[(size_t)row * NC_TOT + t + 256 * j];
        v[j]   = c.x;
        col[j] = __float_as_int(c.y);
    }

    // zero the output row (streaming stores; ordered before scatter by syncs)
    float4* orow4 = (float4*)(out + (size_t)row * N_NODES);
    const float4 zz = make_float4(0.f, 0.f, 0.f, 0.f);
    #pragma unroll
    for (int i = t; i < N_NODES / 4; i += 256) __stcs(orow4 + i, zz);

    __shared__ float qrow[DIM];
    qrow[t]       = Q[(size_t)row * DIM + t];
    qrow[t + 256] = Q[(size_t)row * DIM + t + 256];

    // cached per-thread argmax (tie -> lower column)
    float bv = v[0]; int bc = col[0]; int bj = 0;
    #pragma unroll
    for (int j = 1; j < 4; j++)
        if (v[j] > bv || (v[j] == bv && col[j] < bc)) {
            bv = v[j]; bc = col[j]; bj = j;
        }

    __shared__ float s_val[8];
    __shared__ int   s_idx[8];
    __shared__ int   candi[NCAND];
    __shared__ float exactv[NCAND];
    __shared__ int   s_wi;

    for (int it = 0; it < NCAND; it++) {
        float wv = bv;
        int   wc = bc;
        #pragma unroll
        for (int o = 16; o > 0; o >>= 1) {
            float ov = __shfl_down_sync(0xffffffffu, wv, o);
            int   oc = __shfl_down_sync(0xffffffffu, wc, o);
            if (ov > wv || (ov == wv && oc < wc)) { wv = ov; wc = oc; }
        }
        if (lane == 0) { s_val[wid] = wv; s_idx[wid] = wc; }
        __syncthreads();

        if (t == 0) {
            float best = s_val[0]; int bidx = s_idx[0];
            #pragma unroll
            for (int w = 1; w < 8; w++)
                if (s_val[w] > best || (s_val[w] == best && s_idx[w] < bidx)) {
                    best = s_val[w]; bidx = s_idx[w];
                }
            candi[it] = bidx;
            s_wi = bidx;
        }
        __syncthreads();

        const int wi = s_wi;
        if (bc == wi) {              // this thread owned the winner
            v[bj] = NEG_INF;
            bv = v[0]; bc = col[0]; bj = 0;
            #pragma unroll
            for (int j = 1; j < 4; j++)
                if (v[j] > bv || (v[j] == bv && col[j] < bc)) {
                    bv = v[j]; bc = col[j]; bj = j;
                }
        }
    }

    // ---- exact rescoring: one thread per candidate, strictly serial
    //      ascending-k fp32 FMA chain (reference-order-compatible) ----
    if (t < NCAND) {
        const int cand_c = candi[t];
        const float* krow = Km + (size_t)cand_c * DIM;
        float acc = 0.0f;
        #pragma unroll 8
        for (int k = 0; k < DIM; k++)
            acc = fmaf(qrow[k], krow[k], acc);
        float val = acc / SQRTD;
        val = val + prior_scale[0] * prior[(size_t)row * N_NODES + cand_c];
        exactv[t] = val;
    }
    __syncthreads();   // also orders the row-zeroing before the scatter

    // ---- warp 0: exact top-20 of 32 (ties -> lower column), softmax ----
    if (wid == 0) {
        float val = exactv[lane];
        int   c   = candi[lane];
        float selv = NEG_INF;
        int   seli = 0;
        #pragma unroll
        for (int it = 0; it < TOPK_K; it++) {
            float m = val;
            int   j = c;
            #pragma unroll
            for (int o = 16; o > 0; o >>= 1) {
                float om = __shfl_xor_sync(0xffffffffu, m, o);
                int   oj = __shfl_xor_sync(0xffffffffu, j, o);
                if (om > m || (om == m && oj < j)) { m = om; j = oj; }
            }
            if (lane == it) { selv = m; seli = j; }
            if (val == m && c == j) val = NEG_INF;
        }
        const float mx = __shfl_sync(0xffffffffu, selv, 0);
        float e = (lane < TOPK_K) ? expf(selv - mx) : 0.0f;
        float s = e;
        #pragma unroll
        for (int o = 16; o > 0; o >>= 1)
            s += __shfl_xor_sync(0xffffffffu, s, o);
        if (lane < TOPK_K)
            out[(size_t)row * N_NODES + seli] = e / s;
    }
}

// ===========================================================================
extern "C" void kernel_launch(void* const* d_in, const int* in_sizes, int n_in,
                              void* d_out, int out_size)
{
    const float* h           = (const float*)d_in[0];   // [8192, 512]
    const float* prior_adj   = (const float*)d_in[1];   // [8192, 8192]
    const float* W_q         = (const float*)d_in[2];   // [512, 512]
    const float* W_k         = (const float*)d_in[3];   // [512, 512]
    const float* prior_scale = (const float*)d_in[4];   // scalar
    float* out = (float*)d_out;                         // [8192, 8192]

    float *Qg = nullptr, *Kg = nullptr;
    float2* Cg = nullptr;
    cudaGetSymbolAddress((void**)&Qg, g_Q);
    cudaGetSymbolAddress((void**)&Kg, g_K);
    cudaGetSymbolAddress((void**)&Cg, g_cand);

    // Stage 1: projections + fp32 Q/K + split-bf16 pack
    proj_kernel<<<dim3(DIM / 128, N_NODES / 128, 2), 256>>>(h, W_q, W_k);

    // Stage 2: HMMA split-bf16 GEMM -> per-half-tile top-8 candidates
    cudaFuncSetAttribute(gemm2_kernel,
                         cudaFuncAttributeMaxDynamicSharedMemorySize, G_SMEM_TOTAL);
    gemm2_kernel<<<dim3(N_NODES / 128, N_NODES / 128), 256, G_SMEM_TOTAL>>>(
        prior_adj, prior_scale);

    // Stage 3: candidates -> top-32 -> serial-order exact rescore -> top-20
    topk_softmax_kernel<<<N_NODES, 256>>>(Cg, Qg, Kg, prior_adj, prior_scale, out);
}